// round 14
// baseline (speedup 1.0000x reference)
#include <cuda_runtime.h>

// L2LossWithRebalancing — GB300 sm_103a, round 14.
// BRANCH-FREE single-level resolution for ~98% of pixels:
//   g_line[cell] = (A,B,C,·); v = A*xa + B*xb + C
//   g_w01[cell]  = (w_pos, w_neg);  w = v>=0 ? w_pos : w_neg
//   cnt==1 -> line (0,0,1), w01 (w,w)
//   cnt==2 -> line = s0-s1 coeffs, w01 (w0,w1)   [ties -> lower index]
//   cnt>=3 -> w01.x < 0 sentinel -> batched slots / supercell list (exact)
// Two independent scattered loads per pixel, issued 8-wide across 4 pixels.
// Deterministic fixed-point u64 atomic reduction, graph-replay safe.

#define K_REAL 313
#define GRIDW 256
#define NCELLS (GRIDW * GRIDW)
#define CAPI 16
#define SCAP 64
#define NPIX (16 * 256 * 256)
#define CH_STRIDE 65536
#define IMG_STRIDE 131072
#define LTHREADS 256
#define PXT 4
#define LBLOCKS (NPIX / (LTHREADS * PXT))   // 1024
#define BTHREADS 256
#define BBLOCKS 256                         // one block per 16x16 supercell
#define FIXSCALE 1048576.0                  // 2^20

__device__ float4             g_line[NCELLS];           // 1MB, L2-resident
__device__ float2             g_w01[NCELLS];            // 512KB
__device__ float4             g_cdata[NCELLS * CAPI];   // slots for cnt 3..16
__device__ float4             g_slist[BBLOCKS * SCAP];  // per-supercell lists
__device__ int                g_slen[BBLOCKS];
__device__ float4             g_ctr[K_REAL];            // (2ca,2cb,-|c|^2,w)
__device__ unsigned long long g_acc;                    // zero-init; self-reset
__device__ unsigned int       g_tickets;                // zero-init; wraps

// ---------------------------------------------------------------------------
// Build: block = 16x16-cell supercell, thread = cell.
// score s_k(x) = 2*c_k.x - |c_k|^2 ; argmin dist == argmax score.
// ---------------------------------------------------------------------------
__global__ __launch_bounds__(BTHREADS)
void build_kernel(const float* __restrict__ centers,
                  const float* __restrict__ cw) {
    __shared__ float4 sB[K_REAL];
    __shared__ float4 scand[SCAP];
    __shared__ float  swarp[BTHREADS / 32];
    __shared__ float  s_sth;
    __shared__ int    s_cnt;

    const int t = threadIdx.x;
    for (int i = t; i < K_REAL; i += BTHREADS) {
        float ca = centers[2 * i];
        float cb = centers[2 * i + 1];
        float4 v = make_float4(2.f * ca, 2.f * cb,
                               -(ca * ca + cb * cb), cw[i]);
        sB[i] = v;
        if (blockIdx.x == 0) g_ctr[i] = v;
    }
    __syncthreads();

    const int sx = blockIdx.x & 15;
    const int sy = blockIdx.x >> 4;
    const float sccx = 16.f * sx - 120.f;
    const float sccy = 16.f * sy - 120.f;
    const float scc2 = sccx * sccx + sccy * sccy;

    float m = -1e30f;
    for (int i = t; i < K_REAL; i += BTHREADS) {
        float4 c = sB[i];
        m = fmaxf(m, fmaf(c.x, sccx, fmaf(c.y, sccy, c.z)));
    }
    #pragma unroll
    for (int off = 16; off; off >>= 1)
        m = fmaxf(m, __shfl_xor_sync(0xFFFFFFFFu, m, off));
    if ((t & 31) == 0) swarp[t >> 5] = m;
    __syncthreads();
    if (t == 0) {
        float mm = swarp[0];
        #pragma unroll
        for (int wnum = 1; wnum < BTHREADS / 32; wnum++)
            mm = fmaxf(mm, swarp[wnum]);
        float d2min = fmaxf(scc2 - mm, 0.f);
        float T = sqrtf(d2min) + 22.75f;   // 2*7.5*sqrt2 + sqrt2 + margin
        s_sth = scc2 - T * T;
    }
    __syncthreads();

    // deterministic candidate compaction: warp 0, index-ordered
    if (t < 32) {
        const float sth_sc = s_sth;
        int cnt = 0;
        for (int base = 0; base < K_REAL; base += 32) {
            const int i = base + t;
            bool pred = false;
            float4 c = make_float4(0.f, 0.f, 0.f, 0.f);
            if (i < K_REAL) {
                c = sB[i];
                pred = (fmaf(c.x, sccx, fmaf(c.y, sccy, c.z)) >= sth_sc);
            }
            const unsigned mask = __ballot_sync(0xFFFFFFFFu, pred);
            if (pred) {
                const int pos = cnt + __popc(mask & ((1u << t) - 1u));
                if (pos < SCAP) scand[pos] = c;
            }
            cnt += __popc(mask);
        }
        if (t == 0) s_cnt = cnt;
    }
    __syncthreads();

    const bool use_full = (s_cnt > SCAP);
    const int n = use_full ? K_REAL : s_cnt;

    // persist supercell list for the loss kernel's worst-case path
    if (!use_full) {
        for (int i = t; i < s_cnt; i += BTHREADS)
            g_slist[blockIdx.x * SCAP + i] = scand[i];
        if (t == 0) g_slen[blockIdx.x] = s_cnt;
    } else {
        if (t == 0) g_slen[blockIdx.x] = 0x7FFFFFFF;   // scan g_ctr instead
    }

    const int ix = 16 * sx + (t & 15);
    const int iy = 16 * sy + (t >> 4);
    const float ccx = (float)ix - 127.5f;
    const float ccy = (float)iy - 127.5f;
    const float cc2 = ccx * ccx + ccy * ccy;

    float smax = -1e30f;
    for (int k = 0; k < n; k++) {
        float4 c = use_full ? sB[k] : scand[k];
        smax = fmaxf(smax, fmaf(c.x, ccx, fmaf(c.y, ccy, c.z)));
    }
    float d2min = fmaxf(cc2 - smax, 0.f);
    float T = sqrtf(d2min) + 1.43421356f;  // sqrt(2) diag + fp margin
    const float sth = cc2 - T * T;

    const int cell = (iy << 8) | ix;
    int cnt = 0;
    float4 cand0, cand1;
    float4* slot = &g_cdata[cell * CAPI];
    for (int k = 0; k < n; k++) {
        float4 c = use_full ? sB[k] : scand[k];
        float s = fmaf(c.x, ccx, fmaf(c.y, ccy, c.z));
        if (s >= sth) {
            if (cnt == 0) cand0 = c;
            else if (cnt == 1) cand1 = c;
            if (cnt < CAPI) slot[cnt] = c;
            cnt++;
        }
    }
    float4 ln;
    float2 w01;
    if (cnt == 1) {
        ln  = make_float4(0.f, 0.f, 1.f, 0.f);
        w01 = make_float2(cand0.w, cand0.w);
    } else if (cnt == 2) {
        // v = s0 - s1 ; v>=0 -> cand0 (lower index wins ties, == argmin)
        ln  = make_float4(cand0.x - cand1.x, cand0.y - cand1.y,
                          cand0.z - cand1.z, 0.f);
        w01 = make_float2(cand0.w, cand1.w);
    } else if (cnt <= CAPI) {
        const int pad = (cnt + 3) & ~3;
        const float4 sentinel = make_float4(0.f, 0.f, -1e30f, 0.f);
        for (int j = cnt; j < pad; j++) slot[j] = sentinel;
        ln  = make_float4(0.f, 0.f, 0.f, 0.f);
        w01 = make_float2(-(float)cnt, 0.f);         // sentinel: slots path
    } else {
        ln  = make_float4(0.f, 0.f, 0.f, 0.f);
        w01 = make_float2(-1000.f, 0.f);             // sentinel: list scan
    }
    g_line[cell] = ln;
    g_w01[cell]  = w01;
}

// ---------------------------------------------------------------------------
// Loss: 4 pixels/thread; branch-free single-level resolution (98% of pixels).
// ---------------------------------------------------------------------------
__device__ __forceinline__ void eval4(const float4* cd, float xa, float xb,
                                      float& bs, float& bw) {
    float4 c0 = __ldg(cd + 0);
    float4 c1 = __ldg(cd + 1);
    float4 c2 = __ldg(cd + 2);
    float4 c3 = __ldg(cd + 3);
    float s0 = fmaf(c0.x, xa, fmaf(c0.y, xb, c0.z));
    float s1 = fmaf(c1.x, xa, fmaf(c1.y, xb, c1.z));
    float s2 = fmaf(c2.x, xa, fmaf(c2.y, xb, c2.z));
    float s3 = fmaf(c3.x, xa, fmaf(c3.y, xb, c3.z));
    if (s0 > bs) { bs = s0; bw = c0.w; }
    if (s1 > bs) { bs = s1; bw = c1.w; }
    if (s2 > bs) { bs = s2; bw = c2.w; }
    if (s3 > bs) { bs = s3; bw = c3.w; }
}

__global__ __launch_bounds__(LTHREADS)
void loss_kernel(const float* __restrict__ pred,
                 const float* __restrict__ target,
                 float* __restrict__ out) {
    __shared__ float sred[LTHREADS / 32];

    const int t   = threadIdx.x;
    const int tid = blockIdx.x * LTHREADS + t;
    const int p   = tid * PXT;
    const int b   = p >> 16;
    const int r   = p & 65535;

    const float* tb = target + (size_t)b * IMG_STRIDE + r;
    const float* pb = pred   + (size_t)b * IMG_STRIDE + r;
    const float4 T0 = *(const float4*)tb;
    const float4 T1 = *(const float4*)(tb + CH_STRIDE);
    const float4 P0 = *(const float4*)pb;
    const float4 P1 = *(const float4*)(pb + CH_STRIDE);

    const float f0[4] = {T0.x, T0.y, T0.z, T0.w};
    const float f1[4] = {T1.x, T1.y, T1.z, T1.w};
    const float q0[4] = {P0.x, P0.y, P0.z, P0.w};
    const float q1[4] = {P1.x, P1.y, P1.z, P1.w};

    // phase 1: cells, then 8 independent scattered loads issued together
    int    cells[4];
    float  xa[4], xb[4];
    #pragma unroll
    for (int i = 0; i < 4; i++) {
        xa[i] = f0[i] * 128.f;
        xb[i] = f1[i] * 128.f;
        int ix = __float2int_rd(xa[i] + 128.f);
        int iy = __float2int_rd(xb[i] + 128.f);
        ix = min(max(ix, 0), GRIDW - 1);
        iy = min(max(iy, 0), GRIDW - 1);
        cells[i] = (iy << 8) | ix;
    }
    float4 L[4];
    float2 W[4];
    #pragma unroll
    for (int i = 0; i < 4; i++) L[i] = __ldg(&g_line[cells[i]]);
    #pragma unroll
    for (int i = 0; i < 4; i++) W[i] = __ldg(&g_w01[cells[i]]);

    // phase 2: branch-free resolve; rare sentinel -> exact slow path
    float acc = 0.f;
    #pragma unroll
    for (int i = 0; i < 4; i++) {
        const float v = fmaf(L[i].x, xa[i], fmaf(L[i].y, xb[i], L[i].z));
        float w = (v >= 0.f) ? W[i].x : W[i].y;
        if (W[i].x < 0.f) {                      // cnt>=3 (~2% of pixels)
            float bs = -1e30f, bw = 0.f;
            if (W[i].x > -500.f) {               // 3..16: padded slot batches
                const unsigned cnt = (unsigned)(-W[i].x);
                const float4* cd = &g_cdata[cells[i] * CAPI];
                eval4(cd, xa[i], xb[i], bs, bw);
                if (cnt > 4u) {
                    eval4(cd + 4, xa[i], xb[i], bs, bw);
                    if (cnt > 8u) {
                        eval4(cd + 8, xa[i], xb[i], bs, bw);
                        if (cnt > 12u) eval4(cd + 12, xa[i], xb[i], bs, bw);
                    }
                }
            } else {                             // supercell list / all centers
                const int sc = ((cells[i] >> 12) << 4) | ((cells[i] & 255) >> 4);
                int n = __ldg(&g_slen[sc]);
                const float4* ls;
                if (n <= SCAP) { ls = &g_slist[sc * SCAP]; }
                else           { ls = g_ctr; n = K_REAL; }
                for (int k = 0; k < n; k += 4) {
                    const int k1 = min(k + 1, n - 1);
                    const int k2 = min(k + 2, n - 1);
                    const int k3 = min(k + 3, n - 1);
                    float4 c0 = __ldg(ls + k);
                    float4 c1 = __ldg(ls + k1);
                    float4 c2 = __ldg(ls + k2);
                    float4 c3 = __ldg(ls + k3);
                    float s0 = fmaf(c0.x, xa[i], fmaf(c0.y, xb[i], c0.z));
                    float s1 = fmaf(c1.x, xa[i], fmaf(c1.y, xb[i], c1.z));
                    float s2 = fmaf(c2.x, xa[i], fmaf(c2.y, xb[i], c2.z));
                    float s3 = fmaf(c3.x, xa[i], fmaf(c3.y, xb[i], c3.z));
                    if (s0 > bs) { bs = s0; bw = c0.w; }
                    if (s1 > bs) { bs = s1; bw = c1.w; }
                    if (s2 > bs) { bs = s2; bw = c2.w; }
                    if (s3 > bs) { bs = s3; bw = c3.w; }
                }
            }
            w = bw;
        }

        const float d0 = q0[i] - f0[i];
        const float d1 = q1[i] - f1[i];
        acc = fmaf(fmaf(d0, d0, d1 * d1), w, acc);
    }

    // deterministic reduction: warp -> block -> fixed-point u64 atomic
    #pragma unroll
    for (int off = 16; off; off >>= 1)
        acc += __shfl_down_sync(0xFFFFFFFFu, acc, off);
    if ((t & 31) == 0) sred[t >> 5] = acc;
    __syncthreads();
    if (t < LTHREADS / 32) {
        float v = sred[t];
        #pragma unroll
        for (int off = (LTHREADS / 64); off; off >>= 1)
            v += __shfl_down_sync(0xFFu, v, off);
        if (t == 0) {
            const unsigned long long fx =
                (unsigned long long)__double2ll_rn((double)v * FIXSCALE);
            atomicAdd(&g_acc, fx);
            __threadfence();
            const unsigned ticket = atomicInc(&g_tickets, LBLOCKS - 1);
            if (ticket == LBLOCKS - 1) {
                const unsigned long long total = atomicAdd(&g_acc, 0ULL);
                out[0] = (float)((double)total * (1.0 / FIXSCALE / (double)NPIX));
                __threadfence();
                g_acc = 0ULL;                  // reset for next graph replay
            }
        }
    }
}

extern "C" void kernel_launch(void* const* d_in, const int* in_sizes, int n_in,
                              void* d_out, int out_size) {
    const float* pred    = (const float*)d_in[0];
    const float* target  = (const float*)d_in[1];
    const float* centers = (const float*)d_in[2];
    const float* cw      = (const float*)d_in[3];

    build_kernel<<<BBLOCKS, BTHREADS>>>(centers, cw);
    loss_kernel<<<LBLOCKS, LTHREADS>>>(pred, target, (float*)d_out);
}

// round 15
// speedup vs baseline: 1.0986x; 1.0986x over previous
#include <cuda_runtime.h>
#include <cuda_fp16.h>

// L2LossWithRebalancing — GB300 sm_103a, round 15.
// ONE scattered 16B load per pixel: g_rec[cell] = (A, B, C, wpack)
//   v = A*xa + B*xb + C ;  wpack = f16(w_pos) | f16(w_neg)<<16  (MSB==0)
//   cnt==1 : A,B,C = 0,0,1 ; both halves = w
//   cnt==2 : A,B,C = s0-s1 coeffs (ties -> lower index, == argmin)
//   cnt>=3 : MSB set; low 16 bits = cnt (slots) or 0x7FFF (supercell list)
// fp32 line test => bin decisions bit-exact; only weights are f16-rounded
// (worst-case mean bias 2^-11 < 1e-3 threshold).
// Deterministic fixed-point u64 atomic reduction, graph-replay safe.

#define K_REAL 313
#define GRIDW 256
#define NCELLS (GRIDW * GRIDW)
#define CAPI 8
#define SCAP 64
#define NPIX (16 * 256 * 256)
#define CH_STRIDE 65536
#define IMG_STRIDE 131072
#define LTHREADS 256
#define PXT 4
#define LBLOCKS (NPIX / (LTHREADS * PXT))   // 1024
#define BTHREADS 256
#define BBLOCKS 256                         // one block per 16x16 supercell
#define FIXSCALE 1048576.0                  // 2^20

__device__ float4             g_rec[NCELLS];            // 1MB, L2-resident
__device__ float4             g_cdata[NCELLS * CAPI];   // slots for cnt 3..8
__device__ float4             g_slist[BBLOCKS * SCAP];  // per-supercell lists
__device__ int                g_slen[BBLOCKS];
__device__ float4             g_ctr[K_REAL];            // (2ca,2cb,-|c|^2,w)
__device__ unsigned long long g_acc;                    // zero-init; self-reset
__device__ unsigned int       g_tickets;                // zero-init; wraps

// ---------------------------------------------------------------------------
// Build: block = 16x16-cell supercell, thread = cell.
// score s_k(x) = 2*c_k.x - |c_k|^2 ; argmin dist == argmax score.
// ---------------------------------------------------------------------------
__global__ __launch_bounds__(BTHREADS)
void build_kernel(const float* __restrict__ centers,
                  const float* __restrict__ cw) {
    __shared__ float4 sB[K_REAL];
    __shared__ float4 scand[SCAP];
    __shared__ float  swarp[BTHREADS / 32];
    __shared__ float  s_sth;
    __shared__ int    s_cnt;

    const int t = threadIdx.x;
    for (int i = t; i < K_REAL; i += BTHREADS) {
        float ca = centers[2 * i];
        float cb = centers[2 * i + 1];
        float4 v = make_float4(2.f * ca, 2.f * cb,
                               -(ca * ca + cb * cb), cw[i]);
        sB[i] = v;
        if (blockIdx.x == 0) g_ctr[i] = v;
    }
    __syncthreads();

    const int sx = blockIdx.x & 15;
    const int sy = blockIdx.x >> 4;
    const float sccx = 16.f * sx - 120.f;
    const float sccy = 16.f * sy - 120.f;
    const float scc2 = sccx * sccx + sccy * sccy;

    float m = -1e30f;
    for (int i = t; i < K_REAL; i += BTHREADS) {
        float4 c = sB[i];
        m = fmaxf(m, fmaf(c.x, sccx, fmaf(c.y, sccy, c.z)));
    }
    #pragma unroll
    for (int off = 16; off; off >>= 1)
        m = fmaxf(m, __shfl_xor_sync(0xFFFFFFFFu, m, off));
    if ((t & 31) == 0) swarp[t >> 5] = m;
    __syncthreads();
    if (t == 0) {
        float mm = swarp[0];
        #pragma unroll
        for (int wnum = 1; wnum < BTHREADS / 32; wnum++)
            mm = fmaxf(mm, swarp[wnum]);
        float d2min = fmaxf(scc2 - mm, 0.f);
        float T = sqrtf(d2min) + 22.75f;   // 2*7.5*sqrt2 + sqrt2 + margin
        s_sth = scc2 - T * T;
    }
    __syncthreads();

    // deterministic candidate compaction: warp 0, index-ordered
    if (t < 32) {
        const float sth_sc = s_sth;
        int cnt = 0;
        for (int base = 0; base < K_REAL; base += 32) {
            const int i = base + t;
            bool pred = false;
            float4 c = make_float4(0.f, 0.f, 0.f, 0.f);
            if (i < K_REAL) {
                c = sB[i];
                pred = (fmaf(c.x, sccx, fmaf(c.y, sccy, c.z)) >= sth_sc);
            }
            const unsigned mask = __ballot_sync(0xFFFFFFFFu, pred);
            if (pred) {
                const int pos = cnt + __popc(mask & ((1u << t) - 1u));
                if (pos < SCAP) scand[pos] = c;
            }
            cnt += __popc(mask);
        }
        if (t == 0) s_cnt = cnt;
    }
    __syncthreads();

    const bool use_full = (s_cnt > SCAP);
    const int n = use_full ? K_REAL : s_cnt;

    // persist supercell list for the loss kernel's worst-case path
    if (!use_full) {
        for (int i = t; i < s_cnt; i += BTHREADS)
            g_slist[blockIdx.x * SCAP + i] = scand[i];
        if (t == 0) g_slen[blockIdx.x] = s_cnt;
    } else {
        if (t == 0) g_slen[blockIdx.x] = 0x7FFFFFFF;   // scan g_ctr instead
    }

    const int ix = 16 * sx + (t & 15);
    const int iy = 16 * sy + (t >> 4);
    const float ccx = (float)ix - 127.5f;
    const float ccy = (float)iy - 127.5f;
    const float cc2 = ccx * ccx + ccy * ccy;

    float smax = -1e30f;
    for (int k = 0; k < n; k++) {
        float4 c = use_full ? sB[k] : scand[k];
        smax = fmaxf(smax, fmaf(c.x, ccx, fmaf(c.y, ccy, c.z)));
    }
    float d2min = fmaxf(cc2 - smax, 0.f);
    float T = sqrtf(d2min) + 1.43421356f;  // sqrt(2) diag + fp margin
    const float sth = cc2 - T * T;

    const int cell = (iy << 8) | ix;
    int cnt = 0;
    float4 cand0, cand1;
    float4* slot = &g_cdata[cell * CAPI];
    for (int k = 0; k < n; k++) {
        float4 c = use_full ? sB[k] : scand[k];
        float s = fmaf(c.x, ccx, fmaf(c.y, ccy, c.z));
        if (s >= sth) {
            if (cnt == 0) cand0 = c;
            else if (cnt == 1) cand1 = c;
            if (cnt < CAPI) slot[cnt] = c;
            cnt++;
        }
    }
    float4 rec;
    if (cnt == 1) {
        const unsigned h = (unsigned)__half_as_ushort(__float2half_rn(cand0.w));
        rec = make_float4(0.f, 0.f, 1.f, __uint_as_float(h | (h << 16)));
    } else if (cnt == 2) {
        const unsigned h0 = (unsigned)__half_as_ushort(__float2half_rn(cand0.w));
        const unsigned h1 = (unsigned)__half_as_ushort(__float2half_rn(cand1.w));
        rec = make_float4(cand0.x - cand1.x, cand0.y - cand1.y,
                          cand0.z - cand1.z, __uint_as_float(h0 | (h1 << 16)));
    } else if (cnt <= CAPI) {
        const int pad = (cnt + 3) & ~3;
        const float4 sentinel = make_float4(0.f, 0.f, -1e30f, 0.f);
        for (int j = cnt; j < pad; j++) slot[j] = sentinel;
        rec = make_float4(0.f, 0.f, 0.f,
                          __uint_as_float(0x80000000u | (unsigned)cnt));
    } else {
        rec = make_float4(0.f, 0.f, 0.f,
                          __uint_as_float(0x80000000u | 0x7FFFu));
    }
    g_rec[cell] = rec;
}

// ---------------------------------------------------------------------------
// Loss: 4 pixels/thread; ONE scattered 16B load resolves ~98% of pixels.
// ---------------------------------------------------------------------------
__device__ __forceinline__ void eval4(const float4* cd, float xa, float xb,
                                      float& bs, float& bw) {
    float4 c0 = __ldg(cd + 0);
    float4 c1 = __ldg(cd + 1);
    float4 c2 = __ldg(cd + 2);
    float4 c3 = __ldg(cd + 3);
    float s0 = fmaf(c0.x, xa, fmaf(c0.y, xb, c0.z));
    float s1 = fmaf(c1.x, xa, fmaf(c1.y, xb, c1.z));
    float s2 = fmaf(c2.x, xa, fmaf(c2.y, xb, c2.z));
    float s3 = fmaf(c3.x, xa, fmaf(c3.y, xb, c3.z));
    if (s0 > bs) { bs = s0; bw = c0.w; }
    if (s1 > bs) { bs = s1; bw = c1.w; }
    if (s2 > bs) { bs = s2; bw = c2.w; }
    if (s3 > bs) { bs = s3; bw = c3.w; }
}

__global__ __launch_bounds__(LTHREADS)
void loss_kernel(const float* __restrict__ pred,
                 const float* __restrict__ target,
                 float* __restrict__ out) {
    __shared__ float sred[LTHREADS / 32];

    const int t   = threadIdx.x;
    const int tid = blockIdx.x * LTHREADS + t;
    const int p   = tid * PXT;
    const int b   = p >> 16;
    const int r   = p & 65535;

    const float* tb = target + (size_t)b * IMG_STRIDE + r;
    const float* pb = pred   + (size_t)b * IMG_STRIDE + r;
    const float4 T0 = *(const float4*)tb;
    const float4 T1 = *(const float4*)(tb + CH_STRIDE);
    const float4 P0 = *(const float4*)pb;
    const float4 P1 = *(const float4*)(pb + CH_STRIDE);

    const float f0[4] = {T0.x, T0.y, T0.z, T0.w};
    const float f1[4] = {T1.x, T1.y, T1.z, T1.w};
    const float q0[4] = {P0.x, P0.y, P0.z, P0.w};
    const float q1[4] = {P1.x, P1.y, P1.z, P1.w};

    // phase 1: cells, then 4 independent scattered record loads
    int   cells[4];
    float xa[4], xb[4];
    #pragma unroll
    for (int i = 0; i < 4; i++) {
        xa[i] = f0[i] * 128.f;
        xb[i] = f1[i] * 128.f;
        int ix = __float2int_rd(xa[i] + 128.f);
        int iy = __float2int_rd(xb[i] + 128.f);
        ix = min(max(ix, 0), GRIDW - 1);
        iy = min(max(iy, 0), GRIDW - 1);
        cells[i] = (iy << 8) | ix;
    }
    float4 R[4];
    #pragma unroll
    for (int i = 0; i < 4; i++) R[i] = __ldg(&g_rec[cells[i]]);

    // phase 2: resolve + accumulate
    float acc = 0.f;
    #pragma unroll
    for (int i = 0; i < 4; i++) {
        const unsigned wp = __float_as_uint(R[i].w);
        const float v = fmaf(R[i].x, xa[i], fmaf(R[i].y, xb[i], R[i].z));
        const unsigned hbits = (v >= 0.f) ? (wp & 0xFFFFu) : (wp >> 16);
        float w = __half2float(__ushort_as_half((unsigned short)hbits));
        if (wp & 0x80000000u) {                  // cnt>=3 (~2% of pixels)
            float bs = -1e30f, bw = 0.f;
            const unsigned cnt = wp & 0xFFFFu;
            if (cnt <= (unsigned)CAPI) {         // 3..8: padded slot batches
                const float4* cd = &g_cdata[cells[i] * CAPI];
                eval4(cd, xa[i], xb[i], bs, bw);
                if (cnt > 4u) eval4(cd + 4, xa[i], xb[i], bs, bw);
            } else {                             // supercell list / all centers
                const int sc = ((cells[i] >> 12) << 4) | ((cells[i] & 255) >> 4);
                int n = __ldg(&g_slen[sc]);
                const float4* ls;
                if (n <= SCAP) { ls = &g_slist[sc * SCAP]; }
                else           { ls = g_ctr; n = K_REAL; }
                for (int k = 0; k < n; k += 4) {
                    const int k1 = min(k + 1, n - 1);
                    const int k2 = min(k + 2, n - 1);
                    const int k3 = min(k + 3, n - 1);
                    float4 c0 = __ldg(ls + k);
                    float4 c1 = __ldg(ls + k1);
                    float4 c2 = __ldg(ls + k2);
                    float4 c3 = __ldg(ls + k3);
                    float s0 = fmaf(c0.x, xa[i], fmaf(c0.y, xb[i], c0.z));
                    float s1 = fmaf(c1.x, xa[i], fmaf(c1.y, xb[i], c1.z));
                    float s2 = fmaf(c2.x, xa[i], fmaf(c2.y, xb[i], c2.z));
                    float s3 = fmaf(c3.x, xa[i], fmaf(c3.y, xb[i], c3.z));
                    if (s0 > bs) { bs = s0; bw = c0.w; }
                    if (s1 > bs) { bs = s1; bw = c1.w; }
                    if (s2 > bs) { bs = s2; bw = c2.w; }
                    if (s3 > bs) { bs = s3; bw = c3.w; }
                }
            }
            w = bw;                              // exact fp32 weight
        }

        const float d0 = q0[i] - f0[i];
        const float d1 = q1[i] - f1[i];
        acc = fmaf(fmaf(d0, d0, d1 * d1), w, acc);
    }

    // deterministic reduction: warp -> block -> fixed-point u64 atomic
    #pragma unroll
    for (int off = 16; off; off >>= 1)
        acc += __shfl_down_sync(0xFFFFFFFFu, acc, off);
    if ((t & 31) == 0) sred[t >> 5] = acc;
    __syncthreads();
    if (t < LTHREADS / 32) {
        float v = sred[t];
        #pragma unroll
        for (int off = (LTHREADS / 64); off; off >>= 1)
            v += __shfl_down_sync(0xFFu, v, off);
        if (t == 0) {
            const unsigned long long fx =
                (unsigned long long)__double2ll_rn((double)v * FIXSCALE);
            atomicAdd(&g_acc, fx);
            __threadfence();
            const unsigned ticket = atomicInc(&g_tickets, LBLOCKS - 1);
            if (ticket == LBLOCKS - 1) {
                const unsigned long long total = atomicAdd(&g_acc, 0ULL);
                out[0] = (float)((double)total * (1.0 / FIXSCALE / (double)NPIX));
                __threadfence();
                g_acc = 0ULL;                  // reset for next graph replay
            }
        }
    }
}

extern "C" void kernel_launch(void* const* d_in, const int* in_sizes, int n_in,
                              void* d_out, int out_size) {
    const float* pred    = (const float*)d_in[0];
    const float* target  = (const float*)d_in[1];
    const float* centers = (const float*)d_in[2];
    const float* cw      = (const float*)d_in[3];

    build_kernel<<<BBLOCKS, BTHREADS>>>(centers, cw);
    loss_kernel<<<LBLOCKS, LTHREADS>>>(pred, target, (float*)d_out);
}